// round 15
// baseline (speedup 1.0000x reference)
#include <cuda_runtime.h>
#include <math.h>

#define N_NODES 50000
#define N_EDGES 800000
#define NHEADS  8
#define MULT    16

// Scratch (device globals — no allocation allowed)
__device__ float g_e[(size_t)N_EDGES * NHEADS];   // exp scores (25.6 MB)
__device__ float g_s[(size_t)N_NODES * NHEADS];   // softmax denominators (1.6 MB)

// ---------------------------------------------------------------------------
// Pass 1: one (edge, head) per slot, FOUR slots per thread at stride total/4.
// Array-structured so ptxas front-batches the independent load streams
// (~40 outstanding loads/thread) to cover L2 latency on random q gathers.
// Also zeroes d_out (float2 per thread). Grid exact, no bounds checks.
// ---------------------------------------------------------------------------
__global__ void __launch_bounds__(256) pass1_scores(
    const float* __restrict__ k0, const float* __restrict__ k1,
    const float* __restrict__ q0, const float* __restrict__ q1,
    const int* __restrict__ row_idx, const int* __restrict__ col_idx,
    float2* __restrict__ out_zero)
{
    const int QTR = N_EDGES * NHEADS / 4;   // 1.6M
    int t = blockIdx.x * blockDim.x + threadIdx.x;

    out_zero[t] = make_float2(0.f, 0.f);    // d_out = 3.2M floats = 1.6M float2

    int e[4], h[4], col[4], rw[4];
#pragma unroll
    for (int s = 0; s < 4; s++) {
        int slot = t + s * QTR;
        e[s] = slot >> 3;
        h[s] = slot & 7;
    }
#pragma unroll
    for (int s = 0; s < 4; s++) {
        col[s] = __ldg(col_idx + e[s]);
        rw[s]  = __ldg(row_idx + e[s]);
    }

    float2 ka[4], qa[4];
#pragma unroll
    for (int s = 0; s < 4; s++) {
        ka[s] = *(const float2*)(k0 + (size_t)e[s]   * 16 + 2 * h[s]);
        qa[s] = *(const float2*)(q0 + (size_t)col[s] * 16 + 2 * h[s]);
    }

    float2 kb[4][3], qb[4][3];
#pragma unroll
    for (int s = 0; s < 4; s++) {
        const float2* kp = (const float2*)(k1 + (size_t)e[s]   * 48 + 6 * h[s]);
        const float2* qp = (const float2*)(q1 + (size_t)col[s] * 48 + 6 * h[s]);
#pragma unroll
        for (int j = 0; j < 3; j++) {
            kb[s][j] = kp[j];
            qb[s][j] = qp[j];
        }
    }

#pragma unroll
    for (int s = 0; s < 4; s++) {
        float dot = ka[s].x * qa[s].x + ka[s].y * qa[s].y;
#pragma unroll
        for (int j = 0; j < 3; j++)
            dot += kb[s][j].x * qb[s][j].x + kb[s][j].y * qb[s][j].y;

        float w = expf(dot * 0.125f);   // 1/sqrt(64)
        g_e[t + s * QTR] = w;
        atomicAdd(&g_s[rw[s] * NHEADS + h[s]], w);
    }
}

// ---------------------------------------------------------------------------
// Quad-shuffle: lane r of the 4-lane quad holds a0=a[2r], a1=a[2r+1].
// ---------------------------------------------------------------------------
__device__ __forceinline__ float quad_a(float a0, float a1, int h)
{
    float s0 = __shfl_sync(0xFFFFFFFFu, a0, h >> 1, 4);
    float s1 = __shfl_sync(0xFFFFFFFFu, a1, h >> 1, 4);
    return (h & 1) ? s1 : s0;
}

// ---------------------------------------------------------------------------
// Pass 2 (R7 sector-merged layout) with ILP x2: each thread handles work
// items u and u+HALF2 (HALF2 = 1.6M, % 4 == 0 so q is identical for both
// streams and the quad shuffle structure stays valid for both).
// Interleaved out1 chunks {q, 4+q, 8+q}: every RED instruction covers one
// contiguous 64B piece per edge -> full L2 sector merging. Fused MUFU rcp.
// ---------------------------------------------------------------------------
__global__ void __launch_bounds__(256) pass2_scatter(
    const float* __restrict__ v0, const float* __restrict__ v1,
    const int* __restrict__ row_idx, const int* __restrict__ col_idx,
    float* __restrict__ out0, float* __restrict__ out1)
{
    const int HALF2 = N_EDGES * 4 / 2;   // 1.6M
    int t = blockIdx.x * blockDim.x + threadIdx.x;

    int eA = t >> 2;
    int eB = (t + HALF2) >> 2;
    int q  = t & 3;                      // same for both streams

    int rwA  = __ldg(row_idx + eA);
    int rwB  = __ldg(row_idx + eB);
    int colA = __ldg(col_idx + eA);
    int colB = __ldg(col_idx + eB);

    float2 ewA = *(const float2*)(g_e + (size_t)eA  * NHEADS + 2 * q);
    float2 ewB = *(const float2*)(g_e + (size_t)eB  * NHEADS + 2 * q);
    float2 swA = *(const float2*)(g_s + (size_t)rwA * NHEADS + 2 * q);
    float2 swB = *(const float2*)(g_s + (size_t)rwB * NHEADS + 2 * q);

    float a0A = ewA.x * __fdividef(1.0f, swA.x);
    float a1A = ewA.y * __fdividef(1.0f, swA.y);
    float a0B = ewB.x * __fdividef(1.0f, swB.x);
    float a1B = ewB.y * __fdividef(1.0f, swB.y);

    // ---- out0 chunk q for both streams ----
    {
        float4 vA = __ldg((const float4*)(v0 + (size_t)eA * 16 + 4 * q));
        float4 vB = __ldg((const float4*)(v0 + (size_t)eB * 16 + 4 * q));
        float* pA = out0 + (size_t)colA * 16 + 4 * q;
        float* pB = out0 + (size_t)colB * 16 + 4 * q;
        asm volatile("red.global.add.v4.f32 [%0], {%1, %2, %3, %4};"
                     :: "l"(pA), "f"(vA.x * a0A), "f"(vA.y * a0A),
                        "f"(vA.z * a1A), "f"(vA.w * a1A) : "memory");
        asm volatile("red.global.add.v4.f32 [%0], {%1, %2, %3, %4};"
                     :: "l"(pB), "f"(vB.x * a0B), "f"(vB.y * a0B),
                        "f"(vB.z * a1B), "f"(vB.w * a1B) : "memory");
    }

    // ---- out1 chunks c = 4j+q (j=0..2) for both streams ----
    const float4* vpA = (const float4*)(v1 + (size_t)eA * 48);
    const float4* vpB = (const float4*)(v1 + (size_t)eB * 48);
    float* pA = out1 + (size_t)colA * 48;
    float* pB = out1 + (size_t)colB * 48;

#pragma unroll
    for (int j = 0; j < 3; j++) {
        int c = 4 * j + q;
        int hlo = (2 * c) / 3;
        int hhi = hlo + ((c % 3) == 1 ? 1 : 0);

        float4 vA = __ldg(vpA + c);
        float4 vB = __ldg(vpB + c);

        float mloA = quad_a(a0A, a1A, hlo);
        float mhiA = quad_a(a0A, a1A, hhi);
        float mloB = quad_a(a0B, a1B, hlo);
        float mhiB = quad_a(a0B, a1B, hhi);

        asm volatile("red.global.add.v4.f32 [%0], {%1, %2, %3, %4};"
                     :: "l"(pA + 4 * c), "f"(vA.x * mloA), "f"(vA.y * mloA),
                        "f"(vA.z * mhiA), "f"(vA.w * mhiA) : "memory");
        asm volatile("red.global.add.v4.f32 [%0], {%1, %2, %3, %4};"
                     :: "l"(pB + 4 * c), "f"(vB.x * mloB), "f"(vB.y * mloB),
                        "f"(vB.z * mhiB), "f"(vB.w * mhiB) : "memory");
    }
}

// ---------------------------------------------------------------------------
// Launch.  Inputs: v0, v1, k0, k1, q0, q1, edge_index
// Output: out0 (N*16) ++ out1 (N*48)
// ---------------------------------------------------------------------------
extern "C" void kernel_launch(void* const* d_in, const int* in_sizes, int n_in,
                              void* d_out, int out_size)
{
    const float* v0 = (const float*)d_in[0];
    const float* v1 = (const float*)d_in[1];
    const float* k0 = (const float*)d_in[2];
    const float* k1 = (const float*)d_in[3];
    const float* q0 = (const float*)d_in[4];
    const float* q1 = (const float*)d_in[5];
    const int*   ei = (const int*)  d_in[6];
    const int* row_idx = ei;             // edge_index[0]
    const int* col_idx = ei + N_EDGES;   // edge_index[1]

    float* out0 = (float*)d_out;
    float* out1 = out0 + (size_t)N_NODES * MULT;

    void* s_addr = nullptr;
    cudaGetSymbolAddress(&s_addr, g_s);

    cudaMemsetAsync(s_addr, 0, (size_t)N_NODES * NHEADS * sizeof(float));
    // d_out zeroing folded into pass1

    int qtr = N_EDGES * NHEADS / 4;       // 1.6M, divides 256 exactly
    pass1_scores<<<qtr / 256, 256>>>(k0, k1, q0, q1, row_idx, col_idx,
                                     (float2*)d_out);

    int half2 = N_EDGES * 4 / 2;          // 1.6M, divides 256 exactly
    pass2_scatter<<<half2 / 256, 256>>>(v0, v1, row_idx, col_idx, out0, out1);
}

// round 16
// speedup vs baseline: 1.0096x; 1.0096x over previous
#include <cuda_runtime.h>
#include <math.h>

#define N_NODES 50000
#define N_EDGES 800000
#define NHEADS  8
#define MULT    16

// Scratch (device globals — no allocation allowed)
__device__ float g_e[(size_t)N_EDGES * NHEADS];   // exp scores (25.6 MB)
__device__ float g_s[(size_t)N_NODES * NHEADS];   // softmax denominators (1.6 MB)

// ---------------------------------------------------------------------------
// Pass 1: one (edge, head) per slot, FOUR slots per thread at stride total/4.
// Array-structured so ptxas front-batches the independent load streams
// (~40 outstanding loads/thread) to cover L2 latency on random q gathers.
// Also zeroes d_out (float2 per thread). Grid exact, no bounds checks.
// ---------------------------------------------------------------------------
__global__ void __launch_bounds__(256) pass1_scores(
    const float* __restrict__ k0, const float* __restrict__ k1,
    const float* __restrict__ q0, const float* __restrict__ q1,
    const int* __restrict__ row_idx, const int* __restrict__ col_idx,
    float2* __restrict__ out_zero)
{
    const int QTR = N_EDGES * NHEADS / 4;   // 1.6M
    int t = blockIdx.x * blockDim.x + threadIdx.x;

    out_zero[t] = make_float2(0.f, 0.f);    // d_out = 3.2M floats = 1.6M float2

    int e[4], h[4], col[4], rw[4];
#pragma unroll
    for (int s = 0; s < 4; s++) {
        int slot = t + s * QTR;
        e[s] = slot >> 3;
        h[s] = slot & 7;
    }
#pragma unroll
    for (int s = 0; s < 4; s++) {
        col[s] = __ldg(col_idx + e[s]);
        rw[s]  = __ldg(row_idx + e[s]);
    }

    float2 ka[4], qa[4];
#pragma unroll
    for (int s = 0; s < 4; s++) {
        ka[s] = *(const float2*)(k0 + (size_t)e[s]   * 16 + 2 * h[s]);
        qa[s] = *(const float2*)(q0 + (size_t)col[s] * 16 + 2 * h[s]);
    }

    float2 kb[4][3], qb[4][3];
#pragma unroll
    for (int s = 0; s < 4; s++) {
        const float2* kp = (const float2*)(k1 + (size_t)e[s]   * 48 + 6 * h[s]);
        const float2* qp = (const float2*)(q1 + (size_t)col[s] * 48 + 6 * h[s]);
#pragma unroll
        for (int j = 0; j < 3; j++) {
            kb[s][j] = kp[j];
            qb[s][j] = qp[j];
        }
    }

#pragma unroll
    for (int s = 0; s < 4; s++) {
        float dot = ka[s].x * qa[s].x + ka[s].y * qa[s].y;
#pragma unroll
        for (int j = 0; j < 3; j++)
            dot += kb[s][j].x * qb[s][j].x + kb[s][j].y * qb[s][j].y;

        float w = expf(dot * 0.125f);   // 1/sqrt(64)
        g_e[t + s * QTR] = w;
        atomicAdd(&g_s[rw[s] * NHEADS + h[s]], w);
    }
}

// ---------------------------------------------------------------------------
// Quad-shuffle: lane r of the 4-lane quad holds a0=a[2r], a1=a[2r+1].
// ---------------------------------------------------------------------------
__device__ __forceinline__ float quad_a(float a0, float a1, int h)
{
    float s0 = __shfl_sync(0xFFFFFFFFu, a0, h >> 1, 4);
    float s1 = __shfl_sync(0xFFFFFFFFu, a1, h >> 1, 4);
    return (h & 1) ? s1 : s0;
}

// ---------------------------------------------------------------------------
// Pass 2 (R7 sector-merged layout) with ILP x2: each thread handles work
// items u and u+HALF2 (HALF2 = 1.6M, % 4 == 0 so q is identical for both
// streams and the quad shuffle structure stays valid for both).
// Interleaved out1 chunks {q, 4+q, 8+q}: every RED instruction covers one
// contiguous 64B piece per edge -> full L2 sector merging. Fused MUFU rcp.
// ---------------------------------------------------------------------------
__global__ void __launch_bounds__(256) pass2_scatter(
    const float* __restrict__ v0, const float* __restrict__ v1,
    const int* __restrict__ row_idx, const int* __restrict__ col_idx,
    float* __restrict__ out0, float* __restrict__ out1)
{
    const int HALF2 = N_EDGES * 4 / 2;   // 1.6M
    int t = blockIdx.x * blockDim.x + threadIdx.x;

    int eA = t >> 2;
    int eB = (t + HALF2) >> 2;
    int q  = t & 3;                      // same for both streams

    int rwA  = __ldg(row_idx + eA);
    int rwB  = __ldg(row_idx + eB);
    int colA = __ldg(col_idx + eA);
    int colB = __ldg(col_idx + eB);

    float2 ewA = *(const float2*)(g_e + (size_t)eA  * NHEADS + 2 * q);
    float2 ewB = *(const float2*)(g_e + (size_t)eB  * NHEADS + 2 * q);
    float2 swA = *(const float2*)(g_s + (size_t)rwA * NHEADS + 2 * q);
    float2 swB = *(const float2*)(g_s + (size_t)rwB * NHEADS + 2 * q);

    float a0A = ewA.x * __fdividef(1.0f, swA.x);
    float a1A = ewA.y * __fdividef(1.0f, swA.y);
    float a0B = ewB.x * __fdividef(1.0f, swB.x);
    float a1B = ewB.y * __fdividef(1.0f, swB.y);

    // ---- out0 chunk q for both streams ----
    {
        float4 vA = __ldg((const float4*)(v0 + (size_t)eA * 16 + 4 * q));
        float4 vB = __ldg((const float4*)(v0 + (size_t)eB * 16 + 4 * q));
        float* pA = out0 + (size_t)colA * 16 + 4 * q;
        float* pB = out0 + (size_t)colB * 16 + 4 * q;
        asm volatile("red.global.add.v4.f32 [%0], {%1, %2, %3, %4};"
                     :: "l"(pA), "f"(vA.x * a0A), "f"(vA.y * a0A),
                        "f"(vA.z * a1A), "f"(vA.w * a1A) : "memory");
        asm volatile("red.global.add.v4.f32 [%0], {%1, %2, %3, %4};"
                     :: "l"(pB), "f"(vB.x * a0B), "f"(vB.y * a0B),
                        "f"(vB.z * a1B), "f"(vB.w * a1B) : "memory");
    }

    // ---- out1 chunks c = 4j+q (j=0..2) for both streams ----
    const float4* vpA = (const float4*)(v1 + (size_t)eA * 48);
    const float4* vpB = (const float4*)(v1 + (size_t)eB * 48);
    float* pA = out1 + (size_t)colA * 48;
    float* pB = out1 + (size_t)colB * 48;

#pragma unroll
    for (int j = 0; j < 3; j++) {
        int c = 4 * j + q;
        int hlo = (2 * c) / 3;
        int hhi = hlo + ((c % 3) == 1 ? 1 : 0);

        float4 vA = __ldg(vpA + c);
        float4 vB = __ldg(vpB + c);

        float mloA = quad_a(a0A, a1A, hlo);
        float mhiA = quad_a(a0A, a1A, hhi);
        float mloB = quad_a(a0B, a1B, hlo);
        float mhiB = quad_a(a0B, a1B, hhi);

        asm volatile("red.global.add.v4.f32 [%0], {%1, %2, %3, %4};"
                     :: "l"(pA + 4 * c), "f"(vA.x * mloA), "f"(vA.y * mloA),
                        "f"(vA.z * mhiA), "f"(vA.w * mhiA) : "memory");
        asm volatile("red.global.add.v4.f32 [%0], {%1, %2, %3, %4};"
                     :: "l"(pB + 4 * c), "f"(vB.x * mloB), "f"(vB.y * mloB),
                        "f"(vB.z * mhiB), "f"(vB.w * mhiB) : "memory");
    }
}

// ---------------------------------------------------------------------------
// Launch.  Inputs: v0, v1, k0, k1, q0, q1, edge_index
// Output: out0 (N*16) ++ out1 (N*48)
// ---------------------------------------------------------------------------
extern "C" void kernel_launch(void* const* d_in, const int* in_sizes, int n_in,
                              void* d_out, int out_size)
{
    const float* v0 = (const float*)d_in[0];
    const float* v1 = (const float*)d_in[1];
    const float* k0 = (const float*)d_in[2];
    const float* k1 = (const float*)d_in[3];
    const float* q0 = (const float*)d_in[4];
    const float* q1 = (const float*)d_in[5];
    const int*   ei = (const int*)  d_in[6];
    const int* row_idx = ei;             // edge_index[0]
    const int* col_idx = ei + N_EDGES;   // edge_index[1]

    float* out0 = (float*)d_out;
    float* out1 = out0 + (size_t)N_NODES * MULT;

    void* s_addr = nullptr;
    cudaGetSymbolAddress(&s_addr, g_s);

    cudaMemsetAsync(s_addr, 0, (size_t)N_NODES * NHEADS * sizeof(float));
    // d_out zeroing folded into pass1

    int qtr = N_EDGES * NHEADS / 4;       // 1.6M, divides 256 exactly
    pass1_scores<<<qtr / 256, 256>>>(k0, k1, q0, q1, row_idx, col_idx,
                                     (float2*)d_out);

    int half2 = N_EDGES * 4 / 2;          // 1.6M, divides 256 exactly
    pass2_scatter<<<half2 / 256, 256>>>(v0, v1, row_idx, col_idx, out0, out1);
}